// round 15
// baseline (speedup 1.0000x reference)
#include <cuda_runtime.h>
#include <cuda_fp16.h>
#include <cstdint>
#include <math.h>

// ============================================================================
// CrossAttention, compute_103-legal tensor cores (mma.sync fp16).
// Round 14: GEMM re-tiled 128x128 / 256 threads / BK=64 / 2-stage 64 KB ->
// 2 CTAs per SM (cross-CTA hiding of cp_wait + barrier bubbles).
// attn_ov prefetches v into registers before the logits MMA.
// Numerics identical to round 13 (rel_err canary: 5.336e-4).
// ============================================================================

// ---------------- scratch (device globals; allocation-free) ----------------
__device__ __half g_xh[393216];
__device__ __half g_yh[25165824];
__device__ __half g_wqkvh[1769472];
__device__ __half g_wph[589824];
__device__ __half g_qh[512 * 768];             // q fp16
__device__ __half g_kvh[32768L * 1536];        // [k | v] fp16, ld 1536
__device__ float  g_rowsum[6144];              // sum_j exp(s/8)
__device__ __half g_oh[32768L * 768];          // o_pre * 2^13, fp16

// ============================================================================
// low-level helpers (sm_80-level PTX; legal at compute_103)
// ============================================================================
__device__ __forceinline__ uint32_t smem_u32(const void* p) {
    uint32_t a;
    asm("{ .reg .u64 t; cvta.to.shared.u64 t, %1; cvt.u32.u64 %0, t; }" : "=r"(a) : "l"(p));
    return a;
}
__device__ __forceinline__ void cp_async16(uint32_t s, const void* g) {
    asm volatile("cp.async.cg.shared.global [%0], [%1], 16;\n" :: "r"(s), "l"(g));
}
__device__ __forceinline__ void cp_commit() { asm volatile("cp.async.commit_group;\n"); }
template <int N>
__device__ __forceinline__ void cp_wait() { asm volatile("cp.async.wait_group %0;\n" :: "n"(N)); }
__device__ __forceinline__ void ldsm_x4(uint32_t* r, uint32_t addr) {
    asm volatile("ldmatrix.sync.aligned.m8n8.x4.shared.b16 {%0,%1,%2,%3}, [%4];\n"
                 : "=r"(r[0]), "=r"(r[1]), "=r"(r[2]), "=r"(r[3]) : "r"(addr));
}
__device__ __forceinline__ void mma16816(float* c, const uint32_t* a, const uint32_t* b) {
    asm volatile("mma.sync.aligned.m16n8k16.row.col.f32.f16.f16.f32 "
                 "{%0,%1,%2,%3}, {%4,%5,%6,%7}, {%8,%9}, {%0,%1,%2,%3};\n"
                 : "+f"(c[0]), "+f"(c[1]), "+f"(c[2]), "+f"(c[3])
                 : "r"(a[0]), "r"(a[1]), "r"(a[2]), "r"(a[3]), "r"(b[0]), "r"(b[1]));
}

// ============================================================================
// Single-term HMMA GEMM: C = A[M,K] @ B[N,K]^T
// Block tile 128x128, BK=64, 256 threads (2x4 warps, 64x32 warp tile),
// 2-stage cp.async (64 KB) -> 2 CTAs/SM.
// MODE 0: fp32 out * scale + bias                                  (proj)
// MODE 1: combined kv+q: blockIdx.y<256 -> kv (all fp16 into Ch, ld=ldC);
//         blockIdx.y>=256 -> q rows from Aq, B re-based to Wq, out -> Chq
// ============================================================================
static constexpr int OFF_B  = 16384;           // A tile = 16 KB
static constexpr int STAGE  = 32768;           // + B tile 16 KB
static constexpr int GEMM_SMEM = 2 * STAGE;    // 64 KB

template <int MODE>
__global__ void __launch_bounds__(256, 2) hmma_gemm(
    const __half* __restrict__ A, const __half* __restrict__ Aq,
    const __half* __restrict__ B,
    float* __restrict__ Cf, __half* __restrict__ Ch, __half* __restrict__ Chq,
    const float* __restrict__ bias,
    int K, int ldC, float out_scale)
{
    extern __shared__ char smem[];
    const uint32_t sb = smem_u32(smem);
    const int tid  = threadIdx.x;
    const int wid  = tid >> 5;
    const int lane = tid & 31;
    const int m_warp = (wid & 1) * 64;
    const int n_warp = (wid >> 1) * 32;

    const bool isQ = (MODE == 1) && (blockIdx.y >= 256);
    if (isQ && blockIdx.x >= 6) return;        // q has N=768 only
    const __half* Ap   = isQ ? Aq : A;
    const __half* Bsel = isQ ? (B - 768 * 768) : B;   // q multiplies by Wq
    const size_t arow0 = (size_t)(isQ ? (blockIdx.y - 256) : blockIdx.y) * 128;
    const size_t brow0 = (size_t)blockIdx.x * 128;
    const int nChunks = K >> 6;                // BK=64

    const int lrow = tid >> 3;                 // 0..31
    const int lch  = tid & 7;                  // 16B chunk within 128B row

    auto issue_chunk = [&](int c, int stage) {
        const int k0 = c << 6;
        const uint32_t base = sb + stage * STAGE;
        const size_t gk = (size_t)k0 + lch * 8;
        #pragma unroll
        for (int i = 0; i < 4; i++) {
            const int row = lrow + i * 32;
            const uint32_t so = row * 128 + ((lch ^ (row & 7)) << 4);
            cp_async16(base + so, Ap + (arow0 + row) * (size_t)K + gk);
        }
        #pragma unroll
        for (int i = 0; i < 4; i++) {
            const int row = lrow + i * 32;
            const uint32_t so = row * 128 + ((lch ^ (row & 7)) << 4);
            cp_async16(base + OFF_B + so, Bsel + (brow0 + row) * (size_t)K + gk);
        }
    };

    float acc[4][4][4] = {};

    issue_chunk(0, 0); cp_commit();

    for (int c = 0; c < nChunks; c++) {
        cp_wait<0>();
        __syncthreads();   // all warps past compute(c-1); chunk c visible
        if (c + 1 < nChunks) { issue_chunk(c + 1, (c + 1) & 1); cp_commit(); }

        const uint32_t base = sb + (c & 1) * STAGE;
        #pragma unroll
        for (int ks = 0; ks < 4; ks++) {
            uint32_t bh[4][2];
            {
                const int g = lane >> 3;
                const int nr = ((g >> 1) << 3) + (lane & 7);
                const int kk = ks * 16 + ((g & 1) << 3);
                #pragma unroll
                for (int nh = 0; nh < 2; nh++) {
                    const int r = n_warp + nh * 16 + nr;
                    const uint32_t so = r * 128 + ((((kk >> 3) ^ (r & 7))) << 4);
                    uint32_t r4[4];
                    ldsm_x4(r4, base + OFF_B + so);
                    bh[nh * 2][0] = r4[0]; bh[nh * 2][1] = r4[1];
                    bh[nh * 2 + 1][0] = r4[2]; bh[nh * 2 + 1][1] = r4[3];
                }
            }
            uint32_t afr[4][4];
            const int ar = m_warp + (lane & 15);
            const int akk = ks * 16 + (lane >> 4) * 8;
            #pragma unroll
            for (int mi = 0; mi < 4; mi++) {
                const int r = ar + mi * 16;
                ldsm_x4(afr[mi], base + r * 128 + (((akk >> 3) ^ (r & 7)) << 4));
            }
            #pragma unroll
            for (int mi = 0; mi < 4; mi++)
                #pragma unroll
                for (int ni = 0; ni < 4; ni++)
                    mma16816(acc[mi][ni], afr[mi], bh[ni]);
        }
    }

    // epilogue
    const int mg0 = (int)arow0 + m_warp + (lane >> 2);
    const int ng0 = (int)brow0 + n_warp + (lane & 3) * 2;
    #pragma unroll
    for (int mi = 0; mi < 4; mi++) {
        #pragma unroll
        for (int ni = 0; ni < 4; ni++) {
            const int m = mg0 + mi * 16;
            const int n = ng0 + ni * 8;
            const float* a = acc[mi][ni];
            if (MODE == 0) {
                float2 v0 = { a[0] * out_scale, a[1] * out_scale };
                float2 v1 = { a[2] * out_scale, a[3] * out_scale };
                const float2 bv = *(const float2*)&bias[n];
                v0.x += bv.x; v0.y += bv.y; v1.x += bv.x; v1.y += bv.y;
                *(float2*)&Cf[(size_t)m * ldC + n] = v0;
                *(float2*)&Cf[(size_t)(m + 8) * ldC + n] = v1;
            } else if (isQ) {
                __half2 h0 = { __float2half_rn(a[0]), __float2half_rn(a[1]) };
                __half2 h1 = { __float2half_rn(a[2]), __float2half_rn(a[3]) };
                *(__half2*)&Chq[(size_t)m * 768 + n] = h0;
                *(__half2*)&Chq[(size_t)(m + 8) * 768 + n] = h1;
            } else {  // kv: all columns fp16, ld = ldC (1536)
                __half2 h0 = { __float2half_rn(a[0]), __float2half_rn(a[1]) };
                __half2 h1 = { __float2half_rn(a[2]), __float2half_rn(a[3]) };
                *(__half2*)&Ch[(size_t)m * ldC + n] = h0;
                *(__half2*)&Ch[(size_t)(m + 8) * ldC + n] = h1;
            }
        }
    }
}

// ============================================================================
// Fused conversions (y, Wqkv, Wproj, x -> fp16) + rowsum zero. One launch.
// ============================================================================
__global__ void __launch_bounds__(256) conv_all(
    const float* __restrict__ y,  const float* __restrict__ wqkv,
    const float* __restrict__ wp, const float* __restrict__ x,
    __half* __restrict__ yh, __half* __restrict__ wqkvh,
    __half* __restrict__ wph, __half* __restrict__ xh,
    float* __restrict__ rsum)
{
    const int i = blockIdx.x * blockDim.x + threadIdx.x;
    if (i < 1536) *(float4*)&rsum[i * 4] = make_float4(0.f, 0.f, 0.f, 0.f);

    const float* src; __half* dst; int off;
    if (i < 6291456)      { src = y;    dst = yh;    off = i; }
    else if (i < 6733824) { src = wqkv; dst = wqkvh; off = i - 6291456; }
    else if (i < 6881280) { src = wp;   dst = wph;   off = i - 6733824; }
    else                  { src = x;    dst = xh;    off = i - 6881280; }

    const float4 v = *(const float4*)&src[(size_t)off * 4];
    __half h[4] = { __float2half_rn(v.x), __float2half_rn(v.y),
                    __float2half_rn(v.z), __float2half_rn(v.w) };
    *(uint2*)&dst[(size_t)off * 4] = *(uint2*)h;
}

// ============================================================================
// Shared HMMA logits fragment computation (q 64x64 @ k-chunk 128x64).
// ============================================================================
__device__ __forceinline__ void logits_mma(
    uint32_t q_s, uint32_t k_s, int m_warp, int n_warp, int lane,
    float acc[2][4][4])
{
    #pragma unroll
    for (int ks = 0; ks < 4; ks++) {
        uint32_t bfr[4][2];
        {
            const int g = lane >> 3;
            const int nr = ((g >> 1) << 3) + (lane & 7);
            const int kk = ks * 16 + ((g & 1) << 3);
            #pragma unroll
            for (int nh = 0; nh < 2; nh++) {
                const int r = n_warp + nh * 16 + nr;
                uint32_t r4[4];
                ldsm_x4(r4, k_s + r * 128 + (((kk >> 3) ^ (r & 7)) << 4));
                bfr[nh * 2][0] = r4[0]; bfr[nh * 2][1] = r4[1];
                bfr[nh * 2 + 1][0] = r4[2]; bfr[nh * 2 + 1][1] = r4[3];
            }
        }
        uint32_t afr[2][4];
        const int akk = ks * 16 + (lane >> 4) * 8;
        #pragma unroll
        for (int mi = 0; mi < 2; mi++) {
            const int r = m_warp + mi * 16 + (lane & 15);
            ldsm_x4(afr[mi], q_s + r * 128 + (((akk >> 3) ^ (r & 7)) << 4));
        }
        #pragma unroll
        for (int mi = 0; mi < 2; mi++)
            #pragma unroll
            for (int ni = 0; ni < 4; ni++)
                mma16816(acc[mi][ni], afr[mi], bfr[ni]);
    }
}

// q tile [64x64] + k tile [128x64] -> smem (k from kv buffer, ld 1536)
__device__ __forceinline__ void load_qk_tiles(
    uint32_t q_s, uint32_t k_s,
    const __half* __restrict__ qh, const __half* __restrict__ kvh,
    int b, int h, int j0, int tid)
{
    #pragma unroll
    for (int i = 0; i < 2; i++) {
        const int idx = tid + i * 256;
        const int row = idx >> 3, ch = idx & 7;
        cp_async16(q_s + row * 128 + ((ch ^ (row & 7)) << 4),
                   qh + (size_t)(b * 64 + row) * 768 + h * 64 + ch * 8);
    }
    #pragma unroll
    for (int i = 0; i < 4; i++) {
        const int idx = tid + i * 256;
        const int row = idx >> 3, ch = idx & 7;
        cp_async16(k_s + row * 128 + ((ch ^ (row & 7)) << 4),
                   kvh + (size_t)(b * 4096 + j0 + row) * 1536 + h * 64 + ch * 8);
    }
    cp_commit();
}

// ============================================================================
// Pass 1: rowsum only. grid (32, 96).
// ============================================================================
__global__ void __launch_bounds__(256) attn_rowsum(
    const __half* __restrict__ qh, const __half* __restrict__ kvh,
    float* __restrict__ rowsum)
{
    __shared__ __align__(16) char qbuf[64 * 128];
    __shared__ __align__(16) char kbuf[128 * 128];
    __shared__ float rs_s[64];
    const uint32_t q_s = smem_u32(qbuf);
    const uint32_t k_s = smem_u32(kbuf);

    const int bh = blockIdx.y;
    const int b = bh / 12, h = bh % 12;
    const int j0 = blockIdx.x * 128;
    const int tid = threadIdx.x, wid = tid >> 5, lane = tid & 31;
    const int m_warp = (wid & 1) * 32;
    const int n_warp = (wid >> 1) * 32;

    load_qk_tiles(q_s, k_s, qh, kvh, b, h, j0, tid);
    if (tid < 64) rs_s[tid] = 0.0f;
    cp_wait<0>();
    __syncthreads();

    float acc[2][4][4] = {};
    logits_mma(q_s, k_s, m_warp, n_warp, lane, acc);

    float rloc[2][2] = {};
    #pragma unroll
    for (int mi = 0; mi < 2; mi++)
        #pragma unroll
        for (int ni = 0; ni < 4; ni++) {
            rloc[mi][0] += __expf(acc[mi][ni][0] * 0.125f) + __expf(acc[mi][ni][1] * 0.125f);
            rloc[mi][1] += __expf(acc[mi][ni][2] * 0.125f) + __expf(acc[mi][ni][3] * 0.125f);
        }
    #pragma unroll
    for (int mi = 0; mi < 2; mi++) {
        float v0 = rloc[mi][0], v1 = rloc[mi][1];
        v0 += __shfl_xor_sync(0xffffffffu, v0, 1);
        v0 += __shfl_xor_sync(0xffffffffu, v0, 2);
        v1 += __shfl_xor_sync(0xffffffffu, v1, 1);
        v1 += __shfl_xor_sync(0xffffffffu, v1, 2);
        if ((lane & 3) == 0) {
            const int i0 = m_warp + mi * 16 + (lane >> 2);
            atomicAdd(&rs_s[i0], v0);
            atomicAdd(&rs_s[i0 + 8], v1);
        }
    }
    __syncthreads();
    if (tid < 64) atomicAdd(&rowsum[(size_t)bh * 64 + tid], rs_s[tid]);
}

// ============================================================================
// Pass 2: recompute logits, normalize (8192/rowsum), multiply by v (fp16,
// prefetched into registers before the MMA), write o_pre fp16 [n][c].
// e-tile transposed [j][c] fp16 pitch 68. grid (32, 96).
// ============================================================================
static constexpr int OV_PITCH = 68;                    // halves; 136B rows
static constexpr int OV_Q   = 0;
static constexpr int OV_K   = 8192;
static constexpr int OV_E   = OV_K + 16384;            // 128 x 68 halves
static constexpr int OV_INV = OV_E + 128 * OV_PITCH * 2;
static constexpr int OV_SMEM = OV_INV + 256;           // ~42.2 KB

__global__ void __launch_bounds__(256) attn_ov(
    const __half* __restrict__ qh, const __half* __restrict__ kvh,
    const float* __restrict__ rowsum,
    __half* __restrict__ ohi)
{
    extern __shared__ char smem[];
    const uint32_t sb  = smem_u32(smem);
    const uint32_t q_s = sb + OV_Q;
    const uint32_t k_s = sb + OV_K;
    __half* e_s  = (__half*)(smem + OV_E);       // [j][c], pitch OV_PITCH
    float* inv_s = (float*)(smem + OV_INV);

    const int bh = blockIdx.y;
    const int b = bh / 12, h = bh % 12;
    const int j0 = blockIdx.x * 128;
    const int tid = threadIdx.x, wid = tid >> 5, lane = tid & 31;
    const int m_warp = (wid & 1) * 32;
    const int n_warp = (wid >> 1) * 32;

    load_qk_tiles(q_s, k_s, qh, kvh, b, h, j0, tid);
    if (tid < 64) inv_s[tid] = 8192.0f / rowsum[(size_t)bh * 64 + tid];

    // Prefetch v into registers (independent of MMA; latency hidden by compute)
    uint2 vreg[8];
    #pragma unroll
    for (int it = 0; it < 8; it++) {
        const int idx = tid + it * 256;
        const int j = idx >> 4, c4 = (idx & 15) << 2;
        vreg[it] = *(const uint2*)&kvh[(size_t)(b * 4096 + j0 + j) * 1536 + 768 + h * 64 + c4];
    }

    cp_wait<0>();
    __syncthreads();

    float acc[2][4][4] = {};
    logits_mma(q_s, k_s, m_warp, n_warp, lane, acc);

    // Transposed store: e_s[j][i] = fp16(exp(s/8) * inv[i]).
    #pragma unroll
    for (int mi = 0; mi < 2; mi++) {
        const int i0 = m_warp + mi * 16 + (lane >> 2);
        const float inv0 = inv_s[i0], inv1 = inv_s[i0 + 8];
        #pragma unroll
        for (int ni = 0; ni < 4; ni++) {
            const int n0 = n_warp + ni * 8 + (lane & 3) * 2;
            e_s[n0 * OV_PITCH + i0]           = __float2half_rn(__expf(acc[mi][ni][0] * 0.125f) * inv0);
            e_s[(n0 + 1) * OV_PITCH + i0]     = __float2half_rn(__expf(acc[mi][ni][1] * 0.125f) * inv0);
            e_s[n0 * OV_PITCH + i0 + 8]       = __float2half_rn(__expf(acc[mi][ni][2] * 0.125f) * inv1);
            e_s[(n0 + 1) * OV_PITCH + i0 + 8] = __float2half_rn(__expf(acc[mi][ni][3] * 0.125f) * inv1);
        }
    }
    __syncthreads();

    // o[j][c] = e_s[j][c] * v[j][c] (v from registers)
    #pragma unroll
    for (int it = 0; it < 8; it++) {
        const int idx = tid + it * 256;       // 2048 = 128 j x 16 c-quads
        const int j = idx >> 4, c4 = (idx & 15) << 2;
        const uint2 eraw = *(const uint2*)&e_s[j * OV_PITCH + c4];   // 4 halves
        const __half2 e01 = *(const __half2*)&eraw.x;
        const __half2 e23 = *(const __half2*)&eraw.y;
        const __half2 v01 = *(const __half2*)&vreg[it].x;
        const __half2 v23 = *(const __half2*)&vreg[it].y;
        __half2 o01 = __hmul2(e01, v01);
        __half2 o23 = __hmul2(e23, v23);
        uint2 oraw = { *(uint32_t*)&o01, *(uint32_t*)&o23 };
        const size_t orow = (size_t)(b * 4096 + j0 + j) * 768 + h * 64 + c4;
        *(uint2*)&ohi[orow] = oraw;
    }
}

// ============================================================================
// launch
// ============================================================================
extern "C" void kernel_launch(void* const* d_in, const int* in_sizes, int n_in,
                              void* d_out, int out_size)
{
    const float *x = nullptr, *y = nullptr, *Wqkv = nullptr, *Wproj = nullptr, *bproj = nullptr;
    for (int i = 0; i < n_in; i++) {
        switch (in_sizes[i]) {
            case 393216:   x     = (const float*)d_in[i]; break;
            case 25165824: y     = (const float*)d_in[i]; break;
            case 1769472:  Wqkv  = (const float*)d_in[i]; break;
            case 589824:   Wproj = (const float*)d_in[i]; break;
            case 768:      bproj = (const float*)d_in[i]; break;
        }
    }
    float* out = (float*)d_out;

    __half *xh, *yh, *wqkvh, *wph, *qh, *kvh, *oh;
    float *rsum;
    cudaGetSymbolAddress((void**)&xh,     g_xh);
    cudaGetSymbolAddress((void**)&yh,     g_yh);
    cudaGetSymbolAddress((void**)&wqkvh,  g_wqkvh);
    cudaGetSymbolAddress((void**)&wph,    g_wph);
    cudaGetSymbolAddress((void**)&qh,     g_qh);
    cudaGetSymbolAddress((void**)&kvh,    g_kvh);
    cudaGetSymbolAddress((void**)&rsum,   g_rowsum);
    cudaGetSymbolAddress((void**)&oh,     g_oh);

    cudaFuncSetAttribute((const void*)hmma_gemm<0>, cudaFuncAttributeMaxDynamicSharedMemorySize, GEMM_SMEM);
    cudaFuncSetAttribute((const void*)hmma_gemm<1>, cudaFuncAttributeMaxDynamicSharedMemorySize, GEMM_SMEM);
    cudaFuncSetAttribute((const void*)attn_ov,      cudaFuncAttributeMaxDynamicSharedMemorySize, OV_SMEM);

    // 0) fused conversions + rowsum zero
    conv_all<<<27264, 256>>>(y, Wqkv, Wproj, x, yh, wqkvh, wph, xh, rsum);

    // 1) kv = y @ Wkv^T (all fp16, ld 1536) AND q = x @ Wq^T (merged grid)
    //    kv: y-blocks 0..255 (M=32768/128); q: y-blocks 256..259 (M=512/128)
    hmma_gemm<1><<<dim3(12, 260), 256, GEMM_SMEM>>>(
        yh, xh, wqkvh + 768 * 768, nullptr, kvh, qh, nullptr, 768, 1536, 1.0f);

    // 2) attention pass 1: rowsums
    attn_rowsum<<<dim3(32, 96), 256>>>(qh, kvh, rsum);

    // 3) attention pass 2: o_pre fp16 (scaled 2^13), direct [n][c] layout
    attn_ov<<<dim3(32, 96), 256, OV_SMEM>>>(qh, kvh, rsum, oh);

    // 4) out = o_pre @ W_proj^T * 2^-13 + b_proj
    hmma_gemm<0><<<dim3(6, 256), 256, GEMM_SMEM>>>(
        oh, nullptr, wph, out, nullptr, nullptr, bproj, 768, 768, 1.0f / 8192.0f);
}

// round 16
// speedup vs baseline: 1.0054x; 1.0054x over previous
#include <cuda_runtime.h>
#include <cuda_fp16.h>
#include <cstdint>
#include <math.h>

// ============================================================================
// CrossAttention, compute_103-legal tensor cores (mma.sync fp16).
// Round 16: 3-stage cp.async GEMM pipeline at 2 CTAs/SM (96 KB/CTA);
// attn_ov forced to 3 CTAs/SM via __launch_bounds__(256,3).
// Numerics identical to round 15 (rel_err canary: 5.336e-4).
// ============================================================================

// ---------------- scratch (device globals; allocation-free) ----------------
__device__ __half g_xh[393216];
__device__ __half g_yh[25165824];
__device__ __half g_wqkvh[1769472];
__device__ __half g_wph[589824];
__device__ __half g_qh[512 * 768];             // q fp16
__device__ __half g_kvh[32768L * 1536];        // [k | v] fp16, ld 1536
__device__ float  g_rowsum[6144];              // sum_j exp(s/8)
__device__ __half g_oh[32768L * 768];          // o_pre * 2^13, fp16

// ============================================================================
// low-level helpers (sm_80-level PTX; legal at compute_103)
// ============================================================================
__device__ __forceinline__ uint32_t smem_u32(const void* p) {
    uint32_t a;
    asm("{ .reg .u64 t; cvta.to.shared.u64 t, %1; cvt.u32.u64 %0, t; }" : "=r"(a) : "l"(p));
    return a;
}
__device__ __forceinline__ void cp_async16(uint32_t s, const void* g) {
    asm volatile("cp.async.cg.shared.global [%0], [%1], 16;\n" :: "r"(s), "l"(g));
}
__device__ __forceinline__ void cp_commit() { asm volatile("cp.async.commit_group;\n"); }
template <int N>
__device__ __forceinline__ void cp_wait() { asm volatile("cp.async.wait_group %0;\n" :: "n"(N)); }
__device__ __forceinline__ void ldsm_x4(uint32_t* r, uint32_t addr) {
    asm volatile("ldmatrix.sync.aligned.m8n8.x4.shared.b16 {%0,%1,%2,%3}, [%4];\n"
                 : "=r"(r[0]), "=r"(r[1]), "=r"(r[2]), "=r"(r[3]) : "r"(addr));
}
__device__ __forceinline__ void mma16816(float* c, const uint32_t* a, const uint32_t* b) {
    asm volatile("mma.sync.aligned.m16n8k16.row.col.f32.f16.f16.f32 "
                 "{%0,%1,%2,%3}, {%4,%5,%6,%7}, {%8,%9}, {%0,%1,%2,%3};\n"
                 : "+f"(c[0]), "+f"(c[1]), "+f"(c[2]), "+f"(c[3])
                 : "r"(a[0]), "r"(a[1]), "r"(a[2]), "r"(a[3]), "r"(b[0]), "r"(b[1]));
}

// ============================================================================
// Single-term HMMA GEMM: C = A[M,K] @ B[N,K]^T
// Block tile 128x128, BK=64, 256 threads (2x4 warps, 64x32 warp tile),
// 3-stage cp.async (96 KB) -> 2 CTAs/SM.
// MODE 0: fp32 out * scale + bias                                  (proj)
// MODE 1: combined kv+q: blockIdx.y<256 -> kv (all fp16 into Ch, ld=ldC);
//         blockIdx.y>=256 -> q rows from Aq, B re-based to Wq, out -> Chq
// ============================================================================
static constexpr int OFF_B  = 16384;           // A tile = 16 KB
static constexpr int STAGE  = 32768;           // + B tile 16 KB
static constexpr int GEMM_SMEM = 3 * STAGE;    // 96 KB

template <int MODE>
__global__ void __launch_bounds__(256, 2) hmma_gemm(
    const __half* __restrict__ A, const __half* __restrict__ Aq,
    const __half* __restrict__ B,
    float* __restrict__ Cf, __half* __restrict__ Ch, __half* __restrict__ Chq,
    const float* __restrict__ bias,
    int K, int ldC, float out_scale)
{
    extern __shared__ char smem[];
    const uint32_t sb = smem_u32(smem);
    const int tid  = threadIdx.x;
    const int wid  = tid >> 5;
    const int lane = tid & 31;
    const int m_warp = (wid & 1) * 64;
    const int n_warp = (wid >> 1) * 32;

    const bool isQ = (MODE == 1) && (blockIdx.y >= 256);
    if (isQ && blockIdx.x >= 6) return;        // q has N=768 only
    const __half* Ap   = isQ ? Aq : A;
    const __half* Bsel = isQ ? (B - 768 * 768) : B;   // q multiplies by Wq
    const size_t arow0 = (size_t)(isQ ? (blockIdx.y - 256) : blockIdx.y) * 128;
    const size_t brow0 = (size_t)blockIdx.x * 128;
    const int nChunks = K >> 6;                // BK=64 (12 chunks for K=768)

    const int lrow = tid >> 3;                 // 0..31
    const int lch  = tid & 7;                  // 16B chunk within 128B row

    auto issue_chunk = [&](int c, int stage) {
        const int k0 = c << 6;
        const uint32_t base = sb + stage * STAGE;
        const size_t gk = (size_t)k0 + lch * 8;
        #pragma unroll
        for (int i = 0; i < 4; i++) {
            const int row = lrow + i * 32;
            const uint32_t so = row * 128 + ((lch ^ (row & 7)) << 4);
            cp_async16(base + so, Ap + (arow0 + row) * (size_t)K + gk);
        }
        #pragma unroll
        for (int i = 0; i < 4; i++) {
            const int row = lrow + i * 32;
            const uint32_t so = row * 128 + ((lch ^ (row & 7)) << 4);
            cp_async16(base + OFF_B + so, Bsel + (brow0 + row) * (size_t)K + gk);
        }
    };

    float acc[4][4][4] = {};

    issue_chunk(0, 0); cp_commit();
    issue_chunk(1, 1); cp_commit();            // nChunks = 12 >= 2 always

    int stage = 0, stage2 = 2;                 // stage of chunk c; stage for c+2
    for (int c = 0; c < nChunks; c++) {
        if (c + 1 < nChunks) cp_wait<1>(); else cp_wait<0>();
        __syncthreads();   // all warps past compute(c-1); chunk c visible
        if (c + 2 < nChunks) { issue_chunk(c + 2, stage2); cp_commit(); }

        const uint32_t base = sb + stage * STAGE;
        #pragma unroll
        for (int ks = 0; ks < 4; ks++) {
            uint32_t bh[4][2];
            {
                const int g = lane >> 3;
                const int nr = ((g >> 1) << 3) + (lane & 7);
                const int kk = ks * 16 + ((g & 1) << 3);
                #pragma unroll
                for (int nh = 0; nh < 2; nh++) {
                    const int r = n_warp + nh * 16 + nr;
                    const uint32_t so = r * 128 + ((((kk >> 3) ^ (r & 7))) << 4);
                    uint32_t r4[4];
                    ldsm_x4(r4, base + OFF_B + so);
                    bh[nh * 2][0] = r4[0]; bh[nh * 2][1] = r4[1];
                    bh[nh * 2 + 1][0] = r4[2]; bh[nh * 2 + 1][1] = r4[3];
                }
            }
            uint32_t afr[4][4];
            const int ar = m_warp + (lane & 15);
            const int akk = ks * 16 + (lane >> 4) * 8;
            #pragma unroll
            for (int mi = 0; mi < 4; mi++) {
                const int r = ar + mi * 16;
                ldsm_x4(afr[mi], base + r * 128 + (((akk >> 3) ^ (r & 7)) << 4));
            }
            #pragma unroll
            for (int mi = 0; mi < 4; mi++)
                #pragma unroll
                for (int ni = 0; ni < 4; ni++)
                    mma16816(acc[mi][ni], afr[mi], bh[ni]);
        }
        stage  = (stage == 2)  ? 0 : stage + 1;
        stage2 = (stage2 == 2) ? 0 : stage2 + 1;
    }

    // epilogue
    const int mg0 = (int)arow0 + m_warp + (lane >> 2);
    const int ng0 = (int)brow0 + n_warp + (lane & 3) * 2;
    #pragma unroll
    for (int mi = 0; mi < 4; mi++) {
        #pragma unroll
        for (int ni = 0; ni < 4; ni++) {
            const int m = mg0 + mi * 16;
            const int n = ng0 + ni * 8;
            const float* a = acc[mi][ni];
            if (MODE == 0) {
                float2 v0 = { a[0] * out_scale, a[1] * out_scale };
                float2 v1 = { a[2] * out_scale, a[3] * out_scale };
                const float2 bv = *(const float2*)&bias[n];
                v0.x += bv.x; v0.y += bv.y; v1.x += bv.x; v1.y += bv.y;
                *(float2*)&Cf[(size_t)m * ldC + n] = v0;
                *(float2*)&Cf[(size_t)(m + 8) * ldC + n] = v1;
            } else if (isQ) {
                __half2 h0 = { __float2half_rn(a[0]), __float2half_rn(a[1]) };
                __half2 h1 = { __float2half_rn(a[2]), __float2half_rn(a[3]) };
                *(__half2*)&Chq[(size_t)m * 768 + n] = h0;
                *(__half2*)&Chq[(size_t)(m + 8) * 768 + n] = h1;
            } else {  // kv: all columns fp16, ld = ldC (1536)
                __half2 h0 = { __float2half_rn(a[0]), __float2half_rn(a[1]) };
                __half2 h1 = { __float2half_rn(a[2]), __float2half_rn(a[3]) };
                *(__half2*)&Ch[(size_t)m * ldC + n] = h0;
                *(__half2*)&Ch[(size_t)(m + 8) * ldC + n] = h1;
            }
        }
    }
}

// ============================================================================
// Fused conversions (y, Wqkv, Wproj, x -> fp16) + rowsum zero. One launch.
// ============================================================================
__global__ void __launch_bounds__(256) conv_all(
    const float* __restrict__ y,  const float* __restrict__ wqkv,
    const float* __restrict__ wp, const float* __restrict__ x,
    __half* __restrict__ yh, __half* __restrict__ wqkvh,
    __half* __restrict__ wph, __half* __restrict__ xh,
    float* __restrict__ rsum)
{
    const int i = blockIdx.x * blockDim.x + threadIdx.x;
    if (i < 1536) *(float4*)&rsum[i * 4] = make_float4(0.f, 0.f, 0.f, 0.f);

    const float* src; __half* dst; int off;
    if (i < 6291456)      { src = y;    dst = yh;    off = i; }
    else if (i < 6733824) { src = wqkv; dst = wqkvh; off = i - 6291456; }
    else if (i < 6881280) { src = wp;   dst = wph;   off = i - 6733824; }
    else                  { src = x;    dst = xh;    off = i - 6881280; }

    const float4 v = *(const float4*)&src[(size_t)off * 4];
    __half h[4] = { __float2half_rn(v.x), __float2half_rn(v.y),
                    __float2half_rn(v.z), __float2half_rn(v.w) };
    *(uint2*)&dst[(size_t)off * 4] = *(uint2*)h;
}

// ============================================================================
// Shared HMMA logits fragment computation (q 64x64 @ k-chunk 128x64).
// ============================================================================
__device__ __forceinline__ void logits_mma(
    uint32_t q_s, uint32_t k_s, int m_warp, int n_warp, int lane,
    float acc[2][4][4])
{
    #pragma unroll
    for (int ks = 0; ks < 4; ks++) {
        uint32_t bfr[4][2];
        {
            const int g = lane >> 3;
            const int nr = ((g >> 1) << 3) + (lane & 7);
            const int kk = ks * 16 + ((g & 1) << 3);
            #pragma unroll
            for (int nh = 0; nh < 2; nh++) {
                const int r = n_warp + nh * 16 + nr;
                uint32_t r4[4];
                ldsm_x4(r4, k_s + r * 128 + (((kk >> 3) ^ (r & 7)) << 4));
                bfr[nh * 2][0] = r4[0]; bfr[nh * 2][1] = r4[1];
                bfr[nh * 2 + 1][0] = r4[2]; bfr[nh * 2 + 1][1] = r4[3];
            }
        }
        uint32_t afr[2][4];
        const int akk = ks * 16 + (lane >> 4) * 8;
        #pragma unroll
        for (int mi = 0; mi < 2; mi++) {
            const int r = m_warp + mi * 16 + (lane & 15);
            ldsm_x4(afr[mi], q_s + r * 128 + (((akk >> 3) ^ (r & 7)) << 4));
        }
        #pragma unroll
        for (int mi = 0; mi < 2; mi++)
            #pragma unroll
            for (int ni = 0; ni < 4; ni++)
                mma16816(acc[mi][ni], afr[mi], bfr[ni]);
    }
}

// q tile [64x64] + k tile [128x64] -> smem (k from kv buffer, ld 1536)
__device__ __forceinline__ void load_qk_tiles(
    uint32_t q_s, uint32_t k_s,
    const __half* __restrict__ qh, const __half* __restrict__ kvh,
    int b, int h, int j0, int tid)
{
    #pragma unroll
    for (int i = 0; i < 2; i++) {
        const int idx = tid + i * 256;
        const int row = idx >> 3, ch = idx & 7;
        cp_async16(q_s + row * 128 + ((ch ^ (row & 7)) << 4),
                   qh + (size_t)(b * 64 + row) * 768 + h * 64 + ch * 8);
    }
    #pragma unroll
    for (int i = 0; i < 4; i++) {
        const int idx = tid + i * 256;
        const int row = idx >> 3, ch = idx & 7;
        cp_async16(k_s + row * 128 + ((ch ^ (row & 7)) << 4),
                   kvh + (size_t)(b * 4096 + j0 + row) * 1536 + h * 64 + ch * 8);
    }
    cp_commit();
}

// ============================================================================
// Pass 1: rowsum only. grid (32, 96).
// ============================================================================
__global__ void __launch_bounds__(256) attn_rowsum(
    const __half* __restrict__ qh, const __half* __restrict__ kvh,
    float* __restrict__ rowsum)
{
    __shared__ __align__(16) char qbuf[64 * 128];
    __shared__ __align__(16) char kbuf[128 * 128];
    __shared__ float rs_s[64];
    const uint32_t q_s = smem_u32(qbuf);
    const uint32_t k_s = smem_u32(kbuf);

    const int bh = blockIdx.y;
    const int b = bh / 12, h = bh % 12;
    const int j0 = blockIdx.x * 128;
    const int tid = threadIdx.x, wid = tid >> 5, lane = tid & 31;
    const int m_warp = (wid & 1) * 32;
    const int n_warp = (wid >> 1) * 32;

    load_qk_tiles(q_s, k_s, qh, kvh, b, h, j0, tid);
    if (tid < 64) rs_s[tid] = 0.0f;
    cp_wait<0>();
    __syncthreads();

    float acc[2][4][4] = {};
    logits_mma(q_s, k_s, m_warp, n_warp, lane, acc);

    float rloc[2][2] = {};
    #pragma unroll
    for (int mi = 0; mi < 2; mi++)
        #pragma unroll
        for (int ni = 0; ni < 4; ni++) {
            rloc[mi][0] += __expf(acc[mi][ni][0] * 0.125f) + __expf(acc[mi][ni][1] * 0.125f);
            rloc[mi][1] += __expf(acc[mi][ni][2] * 0.125f) + __expf(acc[mi][ni][3] * 0.125f);
        }
    #pragma unroll
    for (int mi = 0; mi < 2; mi++) {
        float v0 = rloc[mi][0], v1 = rloc[mi][1];
        v0 += __shfl_xor_sync(0xffffffffu, v0, 1);
        v0 += __shfl_xor_sync(0xffffffffu, v0, 2);
        v1 += __shfl_xor_sync(0xffffffffu, v1, 1);
        v1 += __shfl_xor_sync(0xffffffffu, v1, 2);
        if ((lane & 3) == 0) {
            const int i0 = m_warp + mi * 16 + (lane >> 2);
            atomicAdd(&rs_s[i0], v0);
            atomicAdd(&rs_s[i0 + 8], v1);
        }
    }
    __syncthreads();
    if (tid < 64) atomicAdd(&rowsum[(size_t)bh * 64 + tid], rs_s[tid]);
}

// ============================================================================
// Pass 2: recompute logits, normalize (8192/rowsum), multiply by v (fp16,
// prefetched into registers before the MMA), write o_pre fp16 [n][c].
// e-tile transposed [j][c] fp16 pitch 68. grid (32, 96). 3 CTAs/SM.
// ============================================================================
static constexpr int OV_PITCH = 68;                    // halves; 136B rows
static constexpr int OV_Q   = 0;
static constexpr int OV_K   = 8192;
static constexpr int OV_E   = OV_K + 16384;            // 128 x 68 halves
static constexpr int OV_INV = OV_E + 128 * OV_PITCH * 2;
static constexpr int OV_SMEM = OV_INV + 256;           // ~42.2 KB

__global__ void __launch_bounds__(256, 3) attn_ov(
    const __half* __restrict__ qh, const __half* __restrict__ kvh,
    const float* __restrict__ rowsum,
    __half* __restrict__ ohi)
{
    extern __shared__ char smem[];
    const uint32_t sb  = smem_u32(smem);
    const uint32_t q_s = sb + OV_Q;
    const uint32_t k_s = sb + OV_K;
    __half* e_s  = (__half*)(smem + OV_E);       // [j][c], pitch OV_PITCH
    float* inv_s = (float*)(smem + OV_INV);

    const int bh = blockIdx.y;
    const int b = bh / 12, h = bh % 12;
    const int j0 = blockIdx.x * 128;
    const int tid = threadIdx.x, wid = tid >> 5, lane = tid & 31;
    const int m_warp = (wid & 1) * 32;
    const int n_warp = (wid >> 1) * 32;

    load_qk_tiles(q_s, k_s, qh, kvh, b, h, j0, tid);
    if (tid < 64) inv_s[tid] = 8192.0f / rowsum[(size_t)bh * 64 + tid];

    // Prefetch v into registers (independent of MMA; latency hidden by compute)
    uint2 vreg[8];
    #pragma unroll
    for (int it = 0; it < 8; it++) {
        const int idx = tid + it * 256;
        const int j = idx >> 4, c4 = (idx & 15) << 2;
        vreg[it] = *(const uint2*)&kvh[(size_t)(b * 4096 + j0 + j) * 1536 + 768 + h * 64 + c4];
    }

    cp_wait<0>();
    __syncthreads();

    float acc[2][4][4] = {};
    logits_mma(q_s, k_s, m_warp, n_warp, lane, acc);

    // Transposed store: e_s[j][i] = fp16(exp(s/8) * inv[i]).
    #pragma unroll
    for (int mi = 0; mi < 2; mi++) {
        const int i0 = m_warp + mi * 16 + (lane >> 2);
        const float inv0 = inv_s[i0], inv1 = inv_s[i0 + 8];
        #pragma unroll
        for (int ni = 0; ni < 4; ni++) {
            const int n0 = n_warp + ni * 8 + (lane & 3) * 2;
            e_s[n0 * OV_PITCH + i0]           = __float2half_rn(__expf(acc[mi][ni][0] * 0.125f) * inv0);
            e_s[(n0 + 1) * OV_PITCH + i0]     = __float2half_rn(__expf(acc[mi][ni][1] * 0.125f) * inv0);
            e_s[n0 * OV_PITCH + i0 + 8]       = __float2half_rn(__expf(acc[mi][ni][2] * 0.125f) * inv1);
            e_s[(n0 + 1) * OV_PITCH + i0 + 8] = __float2half_rn(__expf(acc[mi][ni][3] * 0.125f) * inv1);
        }
    }
    __syncthreads();

    // o[j][c] = e_s[j][c] * v[j][c] (v from registers)
    #pragma unroll
    for (int it = 0; it < 8; it++) {
        const int idx = tid + it * 256;       // 2048 = 128 j x 16 c-quads
        const int j = idx >> 4, c4 = (idx & 15) << 2;
        const uint2 eraw = *(const uint2*)&e_s[j * OV_PITCH + c4];   // 4 halves
        const __half2 e01 = *(const __half2*)&eraw.x;
        const __half2 e23 = *(const __half2*)&eraw.y;
        const __half2 v01 = *(const __half2*)&vreg[it].x;
        const __half2 v23 = *(const __half2*)&vreg[it].y;
        __half2 o01 = __hmul2(e01, v01);
        __half2 o23 = __hmul2(e23, v23);
        uint2 oraw = { *(uint32_t*)&o01, *(uint32_t*)&o23 };
        const size_t orow = (size_t)(b * 4096 + j0 + j) * 768 + h * 64 + c4;
        *(uint2*)&ohi[orow] = oraw;
    }
}

// ============================================================================
// launch
// ============================================================================
extern "C" void kernel_launch(void* const* d_in, const int* in_sizes, int n_in,
                              void* d_out, int out_size)
{
    const float *x = nullptr, *y = nullptr, *Wqkv = nullptr, *Wproj = nullptr, *bproj = nullptr;
    for (int i = 0; i < n_in; i++) {
        switch (in_sizes[i]) {
            case 393216:   x     = (const float*)d_in[i]; break;
            case 25165824: y     = (const float*)d_in[i]; break;
            case 1769472:  Wqkv  = (const float*)d_in[i]; break;
            case 589824:   Wproj = (const float*)d_in[i]; break;
            case 768:      bproj = (const float*)d_in[i]; break;
        }
    }
    float* out = (float*)d_out;

    __half *xh, *yh, *wqkvh, *wph, *qh, *kvh, *oh;
    float *rsum;
    cudaGetSymbolAddress((void**)&xh,     g_xh);
    cudaGetSymbolAddress((void**)&yh,     g_yh);
    cudaGetSymbolAddress((void**)&wqkvh,  g_wqkvh);
    cudaGetSymbolAddress((void**)&wph,    g_wph);
    cudaGetSymbolAddress((void**)&qh,     g_qh);
    cudaGetSymbolAddress((void**)&kvh,    g_kvh);
    cudaGetSymbolAddress((void**)&rsum,   g_rowsum);
    cudaGetSymbolAddress((void**)&oh,     g_oh);

    cudaFuncSetAttribute((const void*)hmma_gemm<0>, cudaFuncAttributeMaxDynamicSharedMemorySize, GEMM_SMEM);
    cudaFuncSetAttribute((const void*)hmma_gemm<1>, cudaFuncAttributeMaxDynamicSharedMemorySize, GEMM_SMEM);
    cudaFuncSetAttribute((const void*)attn_ov,      cudaFuncAttributeMaxDynamicSharedMemorySize, OV_SMEM);

    // 0) fused conversions + rowsum zero
    conv_all<<<27264, 256>>>(y, Wqkv, Wproj, x, yh, wqkvh, wph, xh, rsum);

    // 1) kv = y @ Wkv^T (all fp16, ld 1536) AND q = x @ Wq^T (merged grid)
    hmma_gemm<1><<<dim3(12, 260), 256, GEMM_SMEM>>>(
        yh, xh, wqkvh + 768 * 768, nullptr, kvh, qh, nullptr, 768, 1536, 1.0f);

    // 2) attention pass 1: rowsums
    attn_rowsum<<<dim3(32, 96), 256>>>(qh, kvh, rsum);

    // 3) attention pass 2: o_pre fp16 (scaled 2^13), direct [n][c] layout
    attn_ov<<<dim3(32, 96), 256, OV_SMEM>>>(qh, kvh, rsum, oh);

    // 4) out = o_pre @ W_proj^T * 2^-13 + b_proj
    hmma_gemm<0><<<dim3(6, 256), 256, GEMM_SMEM>>>(
        oh, nullptr, wph, out, nullptr, nullptr, bproj, 768, 768, 1.0f / 8192.0f);
}